// round 16
// baseline (speedup 1.0000x reference)
#include <cuda_runtime.h>
#include <math.h>

// ---------------------------------------------------------------------------
// QNetBlock: 18-qubit state-vector sim, batch 32.
//   out = | P2 * D2 * P1 * D1 * x | / ||x||
// Per layer D = Phi_out * (tensor RY) * Phi_in (Phi diagonal, RY real).
// RY butterflies in packed f32x2. Bit split: low = bits 0..11, high = 12..17.
// 4-pass schedule (R6 structure — proven best at 107us):
//   pass1: Phi_in,lo(L0) + RY bits 0..11.
//   pass2: [Phi_in,hi(L0)*Phi_out,lo(L0)] + RY 12..17 + Phi_out,hi(L0) + P1.
//   pass3: Phi_in,lo(L1) + RY bits 0..11 (in-place).
//   pass4: Phi_in,hi(L1) + RY 12..17; Phi_out(L1) dropped; P2 + |amp|/||x||
//          (norm reduction folded into pass4; no separate norm kernel).
// R15: __launch_bounds__(256,4) — cap regs at 64 to lift occupancy to
// 4 CTAs/SM (32 warps) with zero instruction-count change.
// ---------------------------------------------------------------------------

#define NB      32
#define NSTATE  (1 << 18)
#define CHUNK   4096
#define NCHK    64

typedef unsigned long long u64;

__device__ u64   g_sa[(size_t)NB * NSTATE];   // 64 MB
__device__ u64   g_sb[(size_t)NB * NSTATE];   // 64 MB
__device__ float g_partial[NB * NCHK];

struct PermM { unsigned m[18]; };

// ---- packed f32x2 helpers --------------------------------------------------
__device__ __forceinline__ u64 pk(float x, float y) {
    u64 r; asm("mov.b64 %0,{%1,%2};" : "=l"(r) : "f"(x), "f"(y)); return r;
}
__device__ __forceinline__ void up(u64 a, float& x, float& y) {
    asm("mov.b64 {%0,%1},%2;" : "=f"(x), "=f"(y) : "l"(a));
}
__device__ __forceinline__ u64 f2mul(u64 a, u64 b) {
    u64 r; asm("mul.rn.f32x2 %0,%1,%2;" : "=l"(r) : "l"(a), "l"(b)); return r;
}
__device__ __forceinline__ u64 f2fma(u64 a, u64 b, u64 c) {
    u64 r; asm("fma.rn.f32x2 %0,%1,%2,%3;" : "=l"(r) : "l"(a), "l"(b), "l"(c)); return r;
}
__device__ __forceinline__ u64 cmulp(u64 a, u64 b) {
    float ax, ay, bx, by; up(a, ax, ay); up(b, bx, by);
    return pk(fmaf(ax, bx, -ay * by), fmaf(ax, by, ay * bx));
}
// RY butterfly on packed complex: A' = c*A - s*B ; B' = s*A + c*B
__device__ __forceinline__ void bfly2(u64& A, u64& B, u64 c2, u64 s2, u64 ns2) {
    u64 tA = f2mul(ns2, B);
    u64 tB = f2mul(c2,  B);
    u64 nA = f2fma(c2, A, tA);
    B      = f2fma(s2, A, tB);
    A      = nA;
}

// swizzle: conflict-free/2-phase-min for all ownership patterns below
__device__ __forceinline__ int sw16(int i) { return i ^ ((i >> 4) & 15); }

// ---------------------------------------------------------------------------
// pass_low: one layer's RY gates on bits 0..11 + Phi_in,lo at load.
// CTA = contiguous 4096-amp chunk; 256 threads x 16 packed amps.
// Ownership A: bits 8..11 (coalesced load); B: 0..3; C: 4..7 (store).
// ---------------------------------------------------------------------------
template<bool FIRST>
__global__ void __launch_bounds__(256, 4)
pass_low(const float* __restrict__ x, const float* __restrict__ params,
         u64* __restrict__ dst, const u64* __restrict__ src)
{
    extern __shared__ u64 smem[];          // 4096 u64 = 32 KB
    __shared__ float sp[54];
    __shared__ u64   C2[12], S2[12], NS2[12], Tin[16];
    __shared__ float wsum[8];

    int t  = threadIdx.x;
    int b  = blockIdx.x >> 6;
    int ch = blockIdx.x & 63;
    int base = b * NSTATE + ch * CHUNK;

    u64 v[16];
    float xr[16];
    if (FIRST) {
        float ss = 0.f;
#pragma unroll
        for (int k = 0; k < 16; k++) {
            float xv = x[base + t + 256 * k];
            xr[k] = xv;
            ss += xv * xv;
        }
#pragma unroll
        for (int o = 16; o; o >>= 1) ss += __shfl_down_sync(0xffffffffu, ss, o);
        if ((t & 31) == 0) wsum[t >> 5] = ss;
    } else {
#pragma unroll
        for (int k = 0; k < 16; k++) v[k] = src[base + t + 256 * k];
    }
    if (t < 54) sp[t] = params[t];
    __syncthreads();                       // sp + wsum ready

    if (FIRST && t == 0) {
        float s = 0.f;
        for (int i = 0; i < 8; i++) s += wsum[i];
        g_partial[blockIdx.x] = s;         // deterministic fixed-order sum
    }

    if (t < 12) {                          // RY for bit p = t (wire 17-t)
        float s, c; sincosf(0.5f * sp[(17 - t) * 3 + 1], &s, &c);
        C2[t] = pk(c, c); S2[t] = pk(s, s); NS2[t] = pk(-s, -s);
    } else if (t >= 32 && t < 48) {        // Phi_in table over bits 8..11
        int k = t - 32; float a = 0.f;
#pragma unroll
        for (int j = 0; j < 4; j++)
            if ((k >> j) & 1) a += sp[(17 - (8 + j)) * 3 + 0];
        float s, c; sincosf(a, &s, &c); Tin[k] = pk(c, s);
    }
    // per-thread Phi_in base: bits 0..7 of t, plus global -sum/2 over bits 0..11
    float ang = 0.f;
#pragma unroll
    for (int p = 0; p < 12; p++) {
        float ph = sp[(17 - p) * 3 + 0];
        ang -= 0.5f * ph;
        if (p < 8 && ((t >> p) & 1)) ang += ph;
    }
    float fs, fc; sincosf(ang, &fs, &fc);
    u64 pf0 = pk(fc, fs);
    __syncthreads();                       // tables ready

    // Phi_in,lo  (FIRST: real input -> one packed mul per amp)
#pragma unroll
    for (int k = 0; k < 16; k++) {
        u64 fk = cmulp(pf0, Tin[k]);
        if (FIRST) v[k] = f2mul(pk(xr[k], xr[k]), fk);
        else       v[k] = cmulp(v[k], fk);
    }

    // Ownership A: RY bits 8..11
#pragma unroll
    for (int kb = 0; kb < 4; kb++) {
        int m = 1 << kb;
        u64 c2 = C2[8 + kb], s2 = S2[8 + kb], n2 = NS2[8 + kb];
#pragma unroll
        for (int k = 0; k < 16; k++)
            if (!(k & m)) bfly2(v[k], v[k + m], c2, s2, n2);
    }
#pragma unroll
    for (int k = 0; k < 16; k++) smem[sw16(t + 256 * k)] = v[k];
    __syncthreads();

    // Ownership B: elem = t*16 + k -> RY bits 0..3
#pragma unroll
    for (int k = 0; k < 16; k++) v[k] = smem[sw16(t * 16 + k)];
#pragma unroll
    for (int kb = 0; kb < 4; kb++) {
        int m = 1 << kb;
        u64 c2 = C2[kb], s2 = S2[kb], n2 = NS2[kb];
#pragma unroll
        for (int k = 0; k < 16; k++)
            if (!(k & m)) bfly2(v[k], v[k + m], c2, s2, n2);
    }
#pragma unroll
    for (int k = 0; k < 16; k++) smem[sw16(t * 16 + k)] = v[k];
    __syncthreads();

    // Ownership C: elem = r + 16k + 256h -> RY bits 4..7, coalesced store
    int r = t & 15, h = t >> 4;
#pragma unroll
    for (int k = 0; k < 16; k++) v[k] = smem[sw16(r + 16 * k + 256 * h)];
#pragma unroll
    for (int kb = 0; kb < 4; kb++) {
        int m = 1 << kb;
        u64 c2 = C2[4 + kb], s2 = S2[4 + kb], n2 = NS2[4 + kb];
#pragma unroll
        for (int k = 0; k < 16; k++)
            if (!(k & m)) bfly2(v[k], v[k + m], c2, s2, n2);
    }
#pragma unroll
    for (int k = 0; k < 16; k++)
        dst[base + r + 16 * k + 256 * h] = v[k];
}

// ---------------------------------------------------------------------------
// pass_high: one layer's RY gates on bits 12..17 in two stages through one
// stride-1 smem transpose, diagonals at load/store, CNOT-ring permutation as
// XOR-mask scatter at store.
// LAST: per-CTA deterministic norm reduction (replaces norm kernel) and
// writes |amp| * invnorm to the float output.
// ---------------------------------------------------------------------------
template<bool LAST>
__global__ void __launch_bounds__(256, 4)
pass_high(const float* __restrict__ params, PermM P,
          const u64* __restrict__ src, u64* __restrict__ dst,
          float* __restrict__ outF)
{
    extern __shared__ u64 stage[];               // 4096 u64 = 32 KB
    __shared__ float sp[54];
    __shared__ u64   C2[6], S2[6], NS2[6], Hin[64], Hout[64];
    __shared__ float sInv;

    int t    = threadIdx.x;
    int hi2  = t >> 6;                           // source bits 16..17 (stage A)
    int b    = blockIdx.x >> 6;
    int fix  = blockIdx.x & 63;                  // source bits 6..11
    int off_lo = (t & 63) | (fix << 6);          // source bits 0..11
    int base = b * NSTATE + off_lo + (hi2 << 16);

    u64 v[16];
#pragma unroll
    for (int k = 0; k < 16; k++) v[k] = src[base + (k << 12)];  // coalesced

    if (t < 54) sp[t] = params[t];
    if (LAST && t == 64) {                       // fold norm: fixed-order sum
        float s = 0.f;
        for (int i = 0; i < NCHK; i++) s += g_partial[b * NCHK + i];
        sInv = 1.0f / sqrtf(s);
    }
    __syncthreads();

    if (t < 6) {                                 // RY for bit 12+t = wire 5-t
        float s, c; sincosf(0.5f * sp[(5 - t) * 3 + 1], &s, &c);
        C2[t] = pk(c, c); S2[t] = pk(s, s); NS2[t] = pk(-s, -s);
    } else if (t >= 64 && t < 128) {             // tables over bits 12..17
        int kk = t - 64;
        float ai = 0.f, ao = 0.f;
#pragma unroll
        for (int j = 0; j < 6; j++) {
            float ph = sp[(5 - j) * 3 + 0];
            float om = sp[(5 - j) * 3 + 2];
            ai -= 0.5f * ph;  ao -= 0.5f * om;
            if ((kk >> j) & 1) { ai += ph; ao += om; }
        }
        float s, c;
        sincosf(ai, &s, &c); Hin[kk] = pk(c, s);
        if (!LAST) { sincosf(ao, &s, &c); Hout[kk] = pk(c, s); }
    }
    u64 pg = pk(1.f, 0.f);                       // Phi_out,lo(L0), !LAST only
    if (!LAST) {
        float ang = 0.f;
#pragma unroll
        for (int p = 0; p < 12; p++) {
            float om = sp[(17 - p) * 3 + 2];
            ang -= 0.5f * om;
            if ((off_lo >> p) & 1) ang += om;
        }
        float s, c; sincosf(ang, &s, &c); pg = pk(c, s);
    }
    __syncthreads();

    // load diagonal: source bits 12..17 = k | hi2<<4
#pragma unroll
    for (int k = 0; k < 16; k++) {
        u64 f = Hin[k | (hi2 << 4)];
        if (!LAST) f = cmulp(pg, f);
        v[k] = cmulp(v[k], f);
    }

    // Stage A: RY bits 12..15 (k bits 0..3)
#pragma unroll
    for (int kb = 0; kb < 4; kb++) {
        int m = 1 << kb;
        u64 c2 = C2[kb], s2 = S2[kb], n2 = NS2[kb];
#pragma unroll
        for (int k = 0; k < 16; k++)
            if (!(k & m)) bfly2(v[k], v[k + m], c2, s2, n2);
    }

    // transpose: local L = srcbits{0..5} | {12..15}<<6 | {16..17}<<10
#pragma unroll
    for (int k = 0; k < 16; k++)
        stage[(t & 63) | (k << 6) | (hi2 << 10)] = v[k];   // stride-1 in lane
    __syncthreads();

    // Stage B: thread covers local 0..7 (src 0..5, 12..13), k' = local 8..11
    // (src 14..17); butterflies on k' bits 2..3 = src bits 16..17.
#pragma unroll
    for (int k = 0; k < 16; k++) v[k] = stage[t + (k << 8)];  // stride-1
#pragma unroll
    for (int kb = 2; kb < 4; kb++) {
        int m = 1 << kb;
        u64 c2 = C2[2 + kb], s2 = S2[2 + kb], n2 = NS2[2 + kb]; // bits 16,17
#pragma unroll
        for (int k = 0; k < 16; k++)
            if (!(k & m)) bfly2(v[k], v[k + m], c2, s2, n2);
    }

    // permutation: source bits 0..5 = t&63, 6..11 = fix, 12..13 = t>>6,
    // 14..17 = k'. Target = XOR of column masks.
    int off2 = off_lo | ((t >> 6) << 12);        // source bits 0..13
    unsigned tb = 0;
#pragma unroll
    for (int p = 0; p < 14; p++)
        tb ^= P.m[p] & (0u - (unsigned)((off2 >> p) & 1));
    unsigned m14 = P.m[14], m15 = P.m[15], m16 = P.m[16], m17 = P.m[17];
    int bb = b * NSTATE;
    float inv = LAST ? sInv : 0.f;
    int hh = (t >> 6) & 3;                       // source bits 12..13

    if (!LAST) {
#pragma unroll
        for (int k = 0; k < 16; k++) {
            unsigned tg = tb;
            if (k & 1) tg ^= m14;
            if (k & 2) tg ^= m15;
            if (k & 4) tg ^= m16;
            if (k & 8) tg ^= m17;
            dst[bb + tg] = cmulp(v[k], Hout[hh | (k << 2)]); // Phi_out,hi
        }
    } else {
#pragma unroll
        for (int k = 0; k < 16; k++) {
            unsigned tg = tb;
            if (k & 1) tg ^= m14;
            if (k & 2) tg ^= m15;
            if (k & 4) tg ^= m16;
            if (k & 8) tg ^= m17;
            float ax, ay; up(v[k], ax, ay);
            outF[bb + tg] = sqrtf(fmaf(ax, ax, ay * ay)) * inv;
        }
    }
}

// ---------------------------------------------------------------------------
// Host side
// ---------------------------------------------------------------------------
static PermM makePerm(int l) {
    PermM P;
    for (int p = 0; p < 18; p++) {
        unsigned idx = 1u << p;
        for (int i = 0; i < 18; i++) {
            int c  = (i + l) % 18;
            int t  = (i + l + 1) % 18;
            int cb = 17 - c;
            int tb = 17 - t;
            idx ^= ((idx >> cb) & 1u) << tb;
        }
        P.m[p] = idx;
    }
    return P;
}

extern "C" void kernel_launch(void* const* d_in, const int* in_sizes, int n_in,
                              void* d_out, int out_size)
{
    const float* x      = (const float*)d_in[0];
    const float* params = (const float*)d_in[1];
    if (n_in >= 2 && in_sizes[0] < in_sizes[1]) {  // defensive input-order guard
        x      = (const float*)d_in[1];
        params = (const float*)d_in[0];
    }

    cudaFuncSetAttribute(pass_low<true>,
                         cudaFuncAttributeMaxDynamicSharedMemorySize, CHUNK * 8);
    cudaFuncSetAttribute(pass_low<false>,
                         cudaFuncAttributeMaxDynamicSharedMemorySize, CHUNK * 8);
    cudaFuncSetAttribute(pass_high<false>,
                         cudaFuncAttributeMaxDynamicSharedMemorySize, CHUNK * 8);
    cudaFuncSetAttribute(pass_high<true>,
                         cudaFuncAttributeMaxDynamicSharedMemorySize, CHUNK * 8);

    PermM P0 = makePerm(0);
    PermM P1 = makePerm(1);

    u64* sa = nullptr; u64* sb = nullptr;
    cudaGetSymbolAddress((void**)&sa, g_sa);
    cudaGetSymbolAddress((void**)&sb, g_sb);

    // Layer 0
    pass_low<true>  <<<NB * NCHK, 256, CHUNK * 8>>>(x, params, sa, nullptr);
    pass_high<false><<<NB * NCHK, 256, CHUNK * 8>>>(params, P0, sa, sb, nullptr);
    // Layer 1 (pass3 in-place)
    pass_low<false> <<<NB * NCHK, 256, CHUNK * 8>>>(nullptr, params + 54, sb, sb);
    pass_high<true> <<<NB * NCHK, 256, CHUNK * 8>>>(params + 54, P1, sb, nullptr,
                                                    (float*)d_out);
}

// round 17
// speedup vs baseline: 1.5497x; 1.5497x over previous
#include <cuda_runtime.h>
#include <math.h>

// ---------------------------------------------------------------------------
// QNetBlock: 18-qubit state-vector sim, batch 32.
//   out = | P2 * D2 * P1 * D1 * x | / ||x||
// Per layer D = Phi_out * (tensor RY) * Phi_in (Phi diagonal, RY real).
// RY butterflies in packed f32x2. Bit split: low = bits 0..11, high = 12..17.
// 4-pass schedule (R6 structure — proven best at 107us, restored exactly):
//   pass1: Phi_in,lo(L0) + RY bits 0..11.
//   pass2: [Phi_in,hi(L0)*Phi_out,lo(L0)] + RY 12..17 + Phi_out,hi(L0) + P1.
//   pass3: Phi_in,lo(L1) + RY bits 0..11 (in-place).
//   pass4: Phi_in,hi(L1) + RY 12..17; Phi_out(L1) dropped; P2 + |amp|/||x||.
// R16 delta vs R6: ONLY the norm kernel is folded into pass4 (thread 60 does
// the same fixed-order 64-term sum -> bit-identical), deleting one launch.
// launch_bounds(256,3): 80 regs, no spills (the (256,4) cap spilled — R15).
// ---------------------------------------------------------------------------

#define NB      32
#define NSTATE  (1 << 18)
#define CHUNK   4096
#define NCHK    64

typedef unsigned long long u64;

__device__ u64   g_sa[(size_t)NB * NSTATE];   // 64 MB
__device__ u64   g_sb[(size_t)NB * NSTATE];   // 64 MB
__device__ float g_partial[NB * NCHK];

struct PermM { unsigned m[18]; };

// ---- packed f32x2 helpers --------------------------------------------------
__device__ __forceinline__ u64 pk(float x, float y) {
    u64 r; asm("mov.b64 %0,{%1,%2};" : "=l"(r) : "f"(x), "f"(y)); return r;
}
__device__ __forceinline__ void up(u64 a, float& x, float& y) {
    asm("mov.b64 {%0,%1},%2;" : "=f"(x), "=f"(y) : "l"(a));
}
__device__ __forceinline__ u64 f2mul(u64 a, u64 b) {
    u64 r; asm("mul.rn.f32x2 %0,%1,%2;" : "=l"(r) : "l"(a), "l"(b)); return r;
}
__device__ __forceinline__ u64 f2fma(u64 a, u64 b, u64 c) {
    u64 r; asm("fma.rn.f32x2 %0,%1,%2,%3;" : "=l"(r) : "l"(a), "l"(b), "l"(c)); return r;
}
__device__ __forceinline__ u64 cmulp(u64 a, u64 b) {
    float ax, ay, bx, by; up(a, ax, ay); up(b, bx, by);
    return pk(fmaf(ax, bx, -ay * by), fmaf(ax, by, ay * bx));
}
// RY butterfly on packed complex: A' = c*A - s*B ; B' = s*A + c*B
__device__ __forceinline__ void bfly2(u64& A, u64& B, u64 c2, u64 s2, u64 ns2) {
    u64 tA = f2mul(ns2, B);
    u64 tB = f2mul(c2,  B);
    u64 nA = f2fma(c2, A, tA);
    B      = f2fma(s2, A, tB);
    A      = nA;
}

// swizzle: conflict-free/2-phase-min for all ownership patterns below
__device__ __forceinline__ int sw16(int i) { return i ^ ((i >> 4) & 15); }

// ---------------------------------------------------------------------------
// pass_low: one layer's RY gates on bits 0..11 + Phi_in,lo at load.
// CTA = contiguous 4096-amp chunk; 256 threads x 16 packed amps.
// Ownership A: bits 8..11 (coalesced load); B: 0..3; C: 4..7 (store).
// ---------------------------------------------------------------------------
template<bool FIRST>
__global__ void __launch_bounds__(256, 3)
pass_low(const float* __restrict__ x, const float* __restrict__ params,
         u64* __restrict__ dst, const u64* __restrict__ src)
{
    extern __shared__ u64 smem[];          // 4096 u64 = 32 KB
    __shared__ float sp[54];
    __shared__ u64   C2[12], S2[12], NS2[12], Tin[16];
    __shared__ float wsum[8];

    int t  = threadIdx.x;
    int b  = blockIdx.x >> 6;
    int ch = blockIdx.x & 63;
    int base = b * NSTATE + ch * CHUNK;

    u64 v[16];
    float xr[16];
    if (FIRST) {
        float ss = 0.f;
#pragma unroll
        for (int k = 0; k < 16; k++) {
            float xv = x[base + t + 256 * k];
            xr[k] = xv;
            ss += xv * xv;
        }
#pragma unroll
        for (int o = 16; o; o >>= 1) ss += __shfl_down_sync(0xffffffffu, ss, o);
        if ((t & 31) == 0) wsum[t >> 5] = ss;
    } else {
#pragma unroll
        for (int k = 0; k < 16; k++) v[k] = src[base + t + 256 * k];
    }
    if (t < 54) sp[t] = params[t];
    __syncthreads();                       // sp + wsum ready

    if (FIRST && t == 0) {
        float s = 0.f;
        for (int i = 0; i < 8; i++) s += wsum[i];
        g_partial[blockIdx.x] = s;         // deterministic fixed-order sum
    }

    if (t < 12) {                          // RY for bit p = t (wire 17-t)
        float s, c; sincosf(0.5f * sp[(17 - t) * 3 + 1], &s, &c);
        C2[t] = pk(c, c); S2[t] = pk(s, s); NS2[t] = pk(-s, -s);
    } else if (t >= 32 && t < 48) {        // Phi_in table over bits 8..11
        int k = t - 32; float a = 0.f;
#pragma unroll
        for (int j = 0; j < 4; j++)
            if ((k >> j) & 1) a += sp[(17 - (8 + j)) * 3 + 0];
        float s, c; sincosf(a, &s, &c); Tin[k] = pk(c, s);
    }
    // per-thread Phi_in base: bits 0..7 of t, plus global -sum/2 over bits 0..11
    float ang = 0.f;
#pragma unroll
    for (int p = 0; p < 12; p++) {
        float ph = sp[(17 - p) * 3 + 0];
        ang -= 0.5f * ph;
        if (p < 8 && ((t >> p) & 1)) ang += ph;
    }
    float fs, fc; sincosf(ang, &fs, &fc);
    u64 pf0 = pk(fc, fs);
    __syncthreads();                       // tables ready

    // Phi_in,lo  (FIRST: real input -> one packed mul per amp)
#pragma unroll
    for (int k = 0; k < 16; k++) {
        u64 fk = cmulp(pf0, Tin[k]);
        if (FIRST) v[k] = f2mul(pk(xr[k], xr[k]), fk);
        else       v[k] = cmulp(v[k], fk);
    }

    // Ownership A: RY bits 8..11
#pragma unroll
    for (int kb = 0; kb < 4; kb++) {
        int m = 1 << kb;
        u64 c2 = C2[8 + kb], s2 = S2[8 + kb], n2 = NS2[8 + kb];
#pragma unroll
        for (int k = 0; k < 16; k++)
            if (!(k & m)) bfly2(v[k], v[k + m], c2, s2, n2);
    }
#pragma unroll
    for (int k = 0; k < 16; k++) smem[sw16(t + 256 * k)] = v[k];
    __syncthreads();

    // Ownership B: elem = t*16 + k -> RY bits 0..3
#pragma unroll
    for (int k = 0; k < 16; k++) v[k] = smem[sw16(t * 16 + k)];
#pragma unroll
    for (int kb = 0; kb < 4; kb++) {
        int m = 1 << kb;
        u64 c2 = C2[kb], s2 = S2[kb], n2 = NS2[kb];
#pragma unroll
        for (int k = 0; k < 16; k++)
            if (!(k & m)) bfly2(v[k], v[k + m], c2, s2, n2);
    }
#pragma unroll
    for (int k = 0; k < 16; k++) smem[sw16(t * 16 + k)] = v[k];
    __syncthreads();

    // Ownership C: elem = r + 16k + 256h -> RY bits 4..7, coalesced store
    int r = t & 15, h = t >> 4;
#pragma unroll
    for (int k = 0; k < 16; k++) v[k] = smem[sw16(r + 16 * k + 256 * h)];
#pragma unroll
    for (int kb = 0; kb < 4; kb++) {
        int m = 1 << kb;
        u64 c2 = C2[4 + kb], s2 = S2[4 + kb], n2 = NS2[4 + kb];
#pragma unroll
        for (int k = 0; k < 16; k++)
            if (!(k & m)) bfly2(v[k], v[k + m], c2, s2, n2);
    }
#pragma unroll
    for (int k = 0; k < 16; k++)
        dst[base + r + 16 * k + 256 * h] = v[k];
}

// ---------------------------------------------------------------------------
// pass_high: one layer's RY gates on bits 12..17 in two stages through one
// stride-1 smem transpose, diagonals at load/store, CNOT-ring permutation as
// XOR-mask scatter at store.
// LAST: thread 60 does the fixed-order norm reduction (replaces norm kernel,
// bit-identical) and all threads write |amp| * invnorm to the float output.
// ---------------------------------------------------------------------------
template<bool LAST>
__global__ void __launch_bounds__(256, 3)
pass_high(const float* __restrict__ params, PermM P,
          const u64* __restrict__ src, u64* __restrict__ dst,
          float* __restrict__ outF)
{
    extern __shared__ u64 stage[];               // 4096 u64 = 32 KB
    __shared__ float sp[54];
    __shared__ u64   C2[6], S2[6], NS2[6], Hin[64], Hout[64];
    __shared__ float sInv;

    int t    = threadIdx.x;
    int hi2  = t >> 6;                           // source bits 16..17 (stage A)
    int b    = blockIdx.x >> 6;
    int fix  = blockIdx.x & 63;                  // source bits 6..11
    int off_lo = (t & 63) | (fix << 6);          // source bits 0..11
    int base = b * NSTATE + off_lo + (hi2 << 16);

    u64 v[16];
#pragma unroll
    for (int k = 0; k < 16; k++) v[k] = src[base + (k << 12)];  // coalesced

    if (t < 54) sp[t] = params[t];
    if (LAST && t == 60) {                       // fold norm: fixed-order sum
        float s = 0.f;
        for (int i = 0; i < NCHK; i++) s += g_partial[b * NCHK + i];
        sInv = 1.0f / sqrtf(s);
    }
    __syncthreads();

    if (t < 6) {                                 // RY for bit 12+t = wire 5-t
        float s, c; sincosf(0.5f * sp[(5 - t) * 3 + 1], &s, &c);
        C2[t] = pk(c, c); S2[t] = pk(s, s); NS2[t] = pk(-s, -s);
    } else if (t >= 64 && t < 128) {             // tables over bits 12..17
        int kk = t - 64;
        float ai = 0.f, ao = 0.f;
#pragma unroll
        for (int j = 0; j < 6; j++) {
            float ph = sp[(5 - j) * 3 + 0];
            float om = sp[(5 - j) * 3 + 2];
            ai -= 0.5f * ph;  ao -= 0.5f * om;
            if ((kk >> j) & 1) { ai += ph; ao += om; }
        }
        float s, c;
        sincosf(ai, &s, &c); Hin[kk] = pk(c, s);
        if (!LAST) { sincosf(ao, &s, &c); Hout[kk] = pk(c, s); }
    }
    u64 pg = pk(1.f, 0.f);                       // Phi_out,lo(L0), !LAST only
    if (!LAST) {
        float ang = 0.f;
#pragma unroll
        for (int p = 0; p < 12; p++) {
            float om = sp[(17 - p) * 3 + 2];
            ang -= 0.5f * om;
            if ((off_lo >> p) & 1) ang += om;
        }
        float s, c; sincosf(ang, &s, &c); pg = pk(c, s);
    }
    __syncthreads();

    // load diagonal: source bits 12..17 = k | hi2<<4
#pragma unroll
    for (int k = 0; k < 16; k++) {
        u64 f = Hin[k | (hi2 << 4)];
        if (!LAST) f = cmulp(pg, f);
        v[k] = cmulp(v[k], f);
    }

    // Stage A: RY bits 12..15 (k bits 0..3)
#pragma unroll
    for (int kb = 0; kb < 4; kb++) {
        int m = 1 << kb;
        u64 c2 = C2[kb], s2 = S2[kb], n2 = NS2[kb];
#pragma unroll
        for (int k = 0; k < 16; k++)
            if (!(k & m)) bfly2(v[k], v[k + m], c2, s2, n2);
    }

    // transpose: local L = srcbits{0..5} | {12..15}<<6 | {16..17}<<10
#pragma unroll
    for (int k = 0; k < 16; k++)
        stage[(t & 63) | (k << 6) | (hi2 << 10)] = v[k];   // stride-1 in lane
    __syncthreads();

    // Stage B: thread covers local 0..7 (src 0..5, 12..13), k' = local 8..11
    // (src 14..17); butterflies on k' bits 2..3 = src bits 16..17.
#pragma unroll
    for (int k = 0; k < 16; k++) v[k] = stage[t + (k << 8)];  // stride-1
#pragma unroll
    for (int kb = 2; kb < 4; kb++) {
        int m = 1 << kb;
        u64 c2 = C2[2 + kb], s2 = S2[2 + kb], n2 = NS2[2 + kb]; // bits 16,17
#pragma unroll
        for (int k = 0; k < 16; k++)
            if (!(k & m)) bfly2(v[k], v[k + m], c2, s2, n2);
    }

    // permutation: source bits 0..5 = t&63, 6..11 = fix, 12..13 = t>>6,
    // 14..17 = k'. Target = XOR of column masks.
    int off2 = off_lo | ((t >> 6) << 12);        // source bits 0..13
    unsigned tb = 0;
#pragma unroll
    for (int p = 0; p < 14; p++)
        tb ^= P.m[p] & (0u - (unsigned)((off2 >> p) & 1));
    unsigned m14 = P.m[14], m15 = P.m[15], m16 = P.m[16], m17 = P.m[17];
    int bb = b * NSTATE;
    float inv = LAST ? sInv : 0.f;
    int hh = (t >> 6) & 3;                       // source bits 12..13

    if (!LAST) {
#pragma unroll
        for (int k = 0; k < 16; k++) {
            unsigned tg = tb;
            if (k & 1) tg ^= m14;
            if (k & 2) tg ^= m15;
            if (k & 4) tg ^= m16;
            if (k & 8) tg ^= m17;
            dst[bb + tg] = cmulp(v[k], Hout[hh | (k << 2)]); // Phi_out,hi
        }
    } else {
#pragma unroll
        for (int k = 0; k < 16; k++) {
            unsigned tg = tb;
            if (k & 1) tg ^= m14;
            if (k & 2) tg ^= m15;
            if (k & 4) tg ^= m16;
            if (k & 8) tg ^= m17;
            float ax, ay; up(v[k], ax, ay);
            outF[bb + tg] = sqrtf(fmaf(ax, ax, ay * ay)) * inv;
        }
    }
}

// ---------------------------------------------------------------------------
// Host side
// ---------------------------------------------------------------------------
static PermM makePerm(int l) {
    PermM P;
    for (int p = 0; p < 18; p++) {
        unsigned idx = 1u << p;
        for (int i = 0; i < 18; i++) {
            int c  = (i + l) % 18;
            int t  = (i + l + 1) % 18;
            int cb = 17 - c;
            int tb = 17 - t;
            idx ^= ((idx >> cb) & 1u) << tb;
        }
        P.m[p] = idx;
    }
    return P;
}

extern "C" void kernel_launch(void* const* d_in, const int* in_sizes, int n_in,
                              void* d_out, int out_size)
{
    const float* x      = (const float*)d_in[0];
    const float* params = (const float*)d_in[1];
    if (n_in >= 2 && in_sizes[0] < in_sizes[1]) {  // defensive input-order guard
        x      = (const float*)d_in[1];
        params = (const float*)d_in[0];
    }

    cudaFuncSetAttribute(pass_low<true>,
                         cudaFuncAttributeMaxDynamicSharedMemorySize, CHUNK * 8);
    cudaFuncSetAttribute(pass_low<false>,
                         cudaFuncAttributeMaxDynamicSharedMemorySize, CHUNK * 8);
    cudaFuncSetAttribute(pass_high<false>,
                         cudaFuncAttributeMaxDynamicSharedMemorySize, CHUNK * 8);
    cudaFuncSetAttribute(pass_high<true>,
                         cudaFuncAttributeMaxDynamicSharedMemorySize, CHUNK * 8);

    PermM P0 = makePerm(0);
    PermM P1 = makePerm(1);

    u64* sa = nullptr; u64* sb = nullptr;
    cudaGetSymbolAddress((void**)&sa, g_sa);
    cudaGetSymbolAddress((void**)&sb, g_sb);

    // Layer 0
    pass_low<true>  <<<NB * NCHK, 256, CHUNK * 8>>>(x, params, sa, nullptr);
    pass_high<false><<<NB * NCHK, 256, CHUNK * 8>>>(params, P0, sa, sb, nullptr);
    // Layer 1 (pass3 in-place)
    pass_low<false> <<<NB * NCHK, 256, CHUNK * 8>>>(nullptr, params + 54, sb, sb);
    pass_high<true> <<<NB * NCHK, 256, CHUNK * 8>>>(params + 54, P1, sb, nullptr,
                                                    (float*)d_out);
}